// round 3
// baseline (speedup 1.0000x reference)
#include <cuda_runtime.h>
#include <cuda_bf16.h>

// FWHT-4096 fp32, radix-64 x 2 rounds, ONE smem exchange (32KB traffic/row-pair
// vs 64KB for radix-16 x 3). 128 threads/CTA = 2 rows x 64 transform-threads.
//
// Round 1: thread u holds e = u + 64m  (bits 6-11 in regs)  -- coalesced LDG.32
// Exchange: element e stored at float4-index loc4 = ((u>>2) ^ (m&7)) + 16m,
//           component (u&3). Writer STS.32 covers all 32 banks/instr; reader
//           LDS.128 conflict-free in every phase (quad = g ^ (lane&7)).
// Round 2: thread u holds e = 64u + k  (bits 0-5 in regs)   -- STG.128 out
//          (lane-strided 256B; same-thread adjacent instrs fill full 32B
//           sectors, L2 merges -> DRAM traffic stays minimal).

#define FWHT_N   4096
#define TPB      128      // 2 rows per CTA, 64 threads per row

__device__ __forceinline__ void butterfly64(float v[64]) {
#pragma unroll
    for (int b = 1; b < 64; b <<= 1) {
#pragma unroll
        for (int k = 0; k < 64; k++) {
            if (!(k & b)) {
                float a = v[k];
                float c = v[k | b];
                v[k]     = a + c;
                v[k | b] = a - c;
            }
        }
    }
}

__global__ __launch_bounds__(TPB)
void QHadamard_40243843564239_kernel(const float* __restrict__ x,
                                     float* __restrict__ out) {
    __shared__ float s[2][FWHT_N];

    const int tid = threadIdx.x;
    const int r   = tid >> 6;      // which of the 2 rows this half-CTA handles
    const int u   = tid & 63;      // transform-thread id within the row

    const size_t row = (size_t)blockIdx.x * 2 + r;
    const float* __restrict__ xin  = x   + row * FWHT_N;
    float* __restrict__       yout = out + row * FWHT_N;
    float* __restrict__       sr   = s[r];

    float v[64];

    // ---- Round 1: bits 6..11 in regs. v[m] = x[u + 64m]. ----
    // Instruction m: lanes u -> 128B contiguous. 64 coalesced LDG.32 (huge MLP).
#pragma unroll
    for (int m = 0; m < 64; m++) {
        v[m] = __ldcs(xin + u + 64 * m);
    }
    butterfly64(v);

    // ---- Exchange write: loc = (u&3) + 4*((u>>2) ^ (m&7)) + 64m ----
    // Per instruction m: bank = (u&3) + 4*((u>>2)^(m&7)) covers all 32 banks.
    {
        const int lo = (u & 3);
        const int hi = (u >> 2);
#pragma unroll
        for (int m = 0; m < 64; m++) {
            sr[lo + ((hi ^ (m & 7)) << 2) + (m << 6)] = v[m];
        }
    }
    __syncthreads();

    // ---- Exchange read: 16x LDS.128, conflict-free. ----
    // float4 g of thread u sits at loc4 = (g ^ (u&7)) + 16u and holds
    // elements e = 64u + 4g + j in component order j.
    {
        const float4* __restrict__ s4 = reinterpret_cast<const float4*>(sr);
        const int sw = u & 7;
        const int b4 = 16 * u;
#pragma unroll
        for (int g = 0; g < 16; g++) {
            float4 f = s4[(g ^ sw) + b4];
            v[4 * g + 0] = f.x;
            v[4 * g + 1] = f.y;
            v[4 * g + 2] = f.z;
            v[4 * g + 3] = f.w;
        }
    }

    // ---- Round 2: bits 0..5 in regs. ----
    butterfly64(v);

    // ---- Store: e = 64u + k, contiguous per thread -> 16 STG.128. ----
    const float scale = 0.015625f;   // 1/sqrt(4096)
    float4* __restrict__ o4 = reinterpret_cast<float4*>(yout + 64 * u);
#pragma unroll
    for (int g = 0; g < 16; g++) {
        float4 f = make_float4(v[4 * g + 0] * scale,
                               v[4 * g + 1] * scale,
                               v[4 * g + 2] * scale,
                               v[4 * g + 3] * scale);
        __stcs(o4 + g, f);
    }
}

extern "C" void kernel_launch(void* const* d_in, const int* in_sizes, int n_in,
                              void* d_out, int out_size) {
    const float* x = (const float*)d_in[0];
    float* out = (float*)d_out;
    const int rows = in_sizes[0] / FWHT_N;   // 8192
    QHadamard_40243843564239_kernel<<<rows / 2, TPB>>>(x, out);
}

// round 5
// speedup vs baseline: 1.4612x; 1.4612x over previous
#include <cuda_runtime.h>
#include <cuda_bf16.h>

// FWHT-4096 fp32. 256 threads/CTA, TWO rows per CTA packed as float2 in smem.
// Radix-16 x 3 rounds, 2 exchanges. Same smem wavefronts/row as the 1-row
// version, but every smem instruction carries both rows -> 33% fewer MIO instrs.
//
// Layouts (S = float2[4096], S[e] = (row0[e], row1[e])):
//  X1: element e at float2-addr A(e) = (e & ~15) + 2*(((e>>1)&7) ^ ((e>>4)&7)) + (e&1)
//      - R1 write: 8x STS.128 (two float2 per instr), octet lanes cover all banks.
//      - R2 read: 16x LDS.64, each half-warp covers banks fully (CF).
//  X2: element e at float2-addr e (no swizzle needed: e mod 16 == lane mod 16
//      on both the R2-write and R3-read patterns; 8B slots -> CF).

#define FWHT_N 4096
#define TPB    256

__device__ __forceinline__ void butterfly16(float v[16]) {
#pragma unroll
    for (int b = 1; b < 16; b <<= 1) {
#pragma unroll
        for (int k = 0; k < 16; k++) {
            if (!(k & b)) {
                float a = v[k];
                float c = v[k | b];
                v[k]     = a + c;
                v[k | b] = a - c;
            }
        }
    }
}

__global__ __launch_bounds__(TPB)
void QHadamard_40243843564239_kernel(const float* __restrict__ x,
                                     float* __restrict__ out) {
    __shared__ float2 s[FWHT_N];   // 32 KB

    const int t = threadIdx.x;
    const int i = t & 15;
    const int w = t >> 4;

    const size_t row0 = (size_t)blockIdx.x * 2;
    const float* __restrict__ xin0  = x   + row0 * FWHT_N;
    const float* __restrict__ xin1  = xin0 + FWHT_N;
    float* __restrict__       yout0 = out + row0 * FWHT_N;
    float* __restrict__       yout1 = yout0 + FWHT_N;

    float v0[16], v1[16];

    // ---- Round 1: bits 0..3 in regs. e = 16t + k. 8x LDG.128, front-batched. ----
    {
        const float4* __restrict__ a4 = reinterpret_cast<const float4*>(xin0 + 16 * t);
        const float4* __restrict__ b4 = reinterpret_cast<const float4*>(xin1 + 16 * t);
        float4 fa[4], fb[4];
#pragma unroll
        for (int q = 0; q < 4; q++) fa[q] = __ldcs(a4 + q);
#pragma unroll
        for (int q = 0; q < 4; q++) fb[q] = __ldcs(b4 + q);
#pragma unroll
        for (int q = 0; q < 4; q++) {
            v0[4*q+0] = fa[q].x; v0[4*q+1] = fa[q].y; v0[4*q+2] = fa[q].z; v0[4*q+3] = fa[q].w;
            v1[4*q+0] = fb[q].x; v1[4*q+1] = fb[q].y; v1[4*q+2] = fb[q].z; v1[4*q+3] = fb[q].w;
        }
    }
    butterfly16(v0);
    butterfly16(v1);

    // ---- X1 write: 8x STS.128. float4 kp holds elements (2kp, 2kp+1) of both rows.
    // float4-addr = 8t + (kp ^ (t&7))  -> octet of lanes covers 8 distinct quads.
    {
        float4* s4 = reinterpret_cast<float4*>(s);
        const int sw = t & 7;
        const int base = 8 * t;
#pragma unroll
        for (int kp = 0; kp < 8; kp++) {
            s4[base + (kp ^ sw)] = make_float4(v0[2*kp], v1[2*kp], v0[2*kp+1], v1[2*kp+1]);
        }
    }
    __syncthreads();

    // ---- Round 2: bits 4..7 in regs. e = i + 16j + 256w. 16x LDS.64 (CF). ----
    {
        const int ihalf = i >> 1;
        const int ibit  = i & 1;
        const int base  = 256 * w;
#pragma unroll
        for (int j = 0; j < 16; j++) {
            // A(e) = 16*(j+16w) + 2*((i>>1) ^ (j&7)) + (i&1)
            float2 f = s[base + 16 * j + 2 * (ihalf ^ (j & 7)) + ibit];
            v0[j] = f.x;
            v1[j] = f.y;
        }
    }
    butterfly16(v0);
    butterfly16(v1);
    __syncthreads();   // everyone done reading X1 before overwriting as X2

    // ---- X2 write: 16x STS.64 at plain addr e (CF: e mod 16 == lane mod 16). ----
    {
        const int base = i + 256 * w;
#pragma unroll
        for (int j = 0; j < 16; j++) {
            s[base + 16 * j] = make_float2(v0[j], v1[j]);
        }
    }
    __syncthreads();

    // ---- Round 3: bits 8..11 in regs. e = t + 256k. 16x LDS.64 (CF). ----
#pragma unroll
    for (int k = 0; k < 16; k++) {
        float2 f = s[t + 256 * k];
        v0[k] = f.x;
        v1[k] = f.y;
    }
    butterfly16(v0);
    butterfly16(v1);

    // ---- Store: coalesced streaming STG.32 per row. ----
    const float scale = 0.015625f;   // 1/sqrt(4096)
#pragma unroll
    for (int k = 0; k < 16; k++) {
        __stcs(&yout0[t + 256 * k], v0[k] * scale);
        __stcs(&yout1[t + 256 * k], v1[k] * scale);
    }
}

extern "C" void kernel_launch(void* const* d_in, const int* in_sizes, int n_in,
                              void* d_out, int out_size) {
    const float* x = (const float*)d_in[0];
    float* out = (float*)d_out;
    const int rows = in_sizes[0] / FWHT_N;   // 8192
    QHadamard_40243843564239_kernel<<<rows / 2, TPB>>>(x, out);
}

// round 10
// speedup vs baseline: 1.6552x; 1.1328x over previous
#include <cuda_runtime.h>
#include <cuda_fp16.h>

// FWHT-4096 fp32. 256 threads/CTA, 2 rows/CTA. Radix-16 x 3 rounds.
// Exchanges stored as __half2 (row0,row1 packed) -> smem bytes HALVED vs fp32.
// Swizzles (verified conflict-free on all 4 access patterns, 4B slots):
//   X1: S1(e) = [bits2-3 ^= (e>>5)&3] [bit4 ^= (e>>8)&1]
//   X2: S2(e) = e ^ (((e>>8)&1)<<4)
// fp16 roundoff ~2.8e-4 RMS per exchange -> ~4e-4 total (threshold 1e-3).

#define FWHT_N 4096
#define TPB    256

__device__ __forceinline__ void butterfly16(float v[16]) {
#pragma unroll
    for (int b = 1; b < 16; b <<= 1) {
#pragma unroll
        for (int k = 0; k < 16; k++) {
            if (!(k & b)) {
                float a = v[k];
                float c = v[k | b];
                v[k]     = a + c;
                v[k | b] = a - c;
            }
        }
    }
}

__global__ __launch_bounds__(TPB)
void QHadamard_40243843564239_kernel(const float* __restrict__ x,
                                     float* __restrict__ out) {
    __shared__ __half2 s[FWHT_N];   // 16 KB

    const int t = threadIdx.x;
    const int i = t & 15;
    const int w = t >> 4;
    const int wbit = w & 1;

    const size_t row0 = (size_t)blockIdx.x * 2;
    const float* __restrict__ xin0  = x   + row0 * FWHT_N;
    const float* __restrict__ xin1  = xin0 + FWHT_N;
    float* __restrict__       yout0 = out + row0 * FWHT_N;
    float* __restrict__       yout1 = yout0 + FWHT_N;

    float v0[16], v1[16];

    // ---- Round 1: bits 0..3 in regs. e = 16t + k. 8x LDG.128 front-batched. ----
    {
        const float4* __restrict__ a4 = reinterpret_cast<const float4*>(xin0 + 16 * t);
        const float4* __restrict__ b4 = reinterpret_cast<const float4*>(xin1 + 16 * t);
        float4 fa[4], fb[4];
#pragma unroll
        for (int q = 0; q < 4; q++) fa[q] = __ldcs(a4 + q);
#pragma unroll
        for (int q = 0; q < 4; q++) fb[q] = __ldcs(b4 + q);
#pragma unroll
        for (int q = 0; q < 4; q++) {
            v0[4*q+0] = fa[q].x; v0[4*q+1] = fa[q].y; v0[4*q+2] = fa[q].z; v0[4*q+3] = fa[q].w;
            v1[4*q+0] = fb[q].x; v1[4*q+1] = fb[q].y; v1[4*q+2] = fb[q].z; v1[4*q+3] = fb[q].w;
        }
    }
    butterfly16(v0);
    butterfly16(v1);

    // ---- X1 write: 4x STS.128 (uint4 = 4 half2 slots = elems 4q..4q+3). ----
    // unit index u = 4*t' + (q ^ ((t>>1)&3)),  t' = t ^ ((t>>4)&1).
    {
        uint4* s16 = reinterpret_cast<uint4*>(s);
        const int tp   = t ^ ((t >> 4) & 1);
        const int swz  = (t >> 1) & 3;
        const int base = 4 * tp;
#pragma unroll
        for (int q = 0; q < 4; q++) {
            __half2 h0 = __floats2half2_rn(v0[4*q+0], v1[4*q+0]);
            __half2 h1 = __floats2half2_rn(v0[4*q+1], v1[4*q+1]);
            __half2 h2 = __floats2half2_rn(v0[4*q+2], v1[4*q+2]);
            __half2 h3 = __floats2half2_rn(v0[4*q+3], v1[4*q+3]);
            uint4 u;
            u.x = *reinterpret_cast<unsigned*>(&h0);
            u.y = *reinterpret_cast<unsigned*>(&h1);
            u.z = *reinterpret_cast<unsigned*>(&h2);
            u.w = *reinterpret_cast<unsigned*>(&h3);
            s16[base + (q ^ swz)] = u;
        }
    }
    __syncthreads();

    // ---- Round 2: bits 4..7 in regs. e = i + 16j + 256w. ----
    // S1 = (i&3) + 4*((i>>2) ^ ((j>>1)&3)) + 16*(j ^ wbit) + 256*w   (CF)
    {
        const int ilo = i & 3;
        const int ihi = i >> 2;
        const int base = 256 * w;
#pragma unroll
        for (int j = 0; j < 16; j++) {
            const int idx = ilo + ((ihi ^ ((j >> 1) & 3)) << 2) + ((j ^ wbit) << 4) + base;
            float2 f = __half22float2(s[idx]);
            v0[j] = f.x;
            v1[j] = f.y;
        }
    }
    butterfly16(v0);
    butterfly16(v1);
    __syncthreads();   // all X1 reads done before overwriting as X2

    // ---- X2 write: S2 = i + 16*(j ^ wbit) + 256*w   (CF) ----
    {
        const int base = i + 256 * w;
#pragma unroll
        for (int j = 0; j < 16; j++) {
            s[base + ((j ^ wbit) << 4)] = __floats2half2_rn(v0[j], v1[j]);
        }
    }
    __syncthreads();

    // ---- Round 3: bits 8..11 in regs. e = t + 256k. ----
    // S2 = (t ^ ((k&1)<<4)) + 256k   (CF: bank = t mod 32 permuted)
#pragma unroll
    for (int k = 0; k < 16; k++) {
        const int idx = (t ^ ((k & 1) << 4)) + (k << 8);
        float2 f = __half22float2(s[idx]);
        v0[k] = f.x;
        v1[k] = f.y;
    }
    butterfly16(v0);
    butterfly16(v1);

    // ---- Store: coalesced streaming STG.32 per row. ----
    const float scale = 0.015625f;   // 1/sqrt(4096)
#pragma unroll
    for (int k = 0; k < 16; k++) {
        __stcs(&yout0[t + 256 * k], v0[k] * scale);
        __stcs(&yout1[t + 256 * k], v1[k] * scale);
    }
}

extern "C" void kernel_launch(void* const* d_in, const int* in_sizes, int n_in,
                              void* d_out, int out_size) {
    const float* x = (const float*)d_in[0];
    float* out = (float*)d_out;
    const int rows = in_sizes[0] / FWHT_N;   // 8192
    QHadamard_40243843564239_kernel<<<rows / 2, TPB>>>(x, out);
}